// round 12
// baseline (speedup 1.0000x reference)
#include <cuda_runtime.h>
#include <math.h>

#define TS 512
#define BN 128
#define IND 32
#define HN 512
#define ON 8
#define PN 64

// per-CTA fx slab: [cta][t][bb][hl]  (134 MB scratch)
__device__ float g_fxp[(size_t)BN * TS * 8 * 64];
// software barrier flags: 16 groups x 8 CTAs, sector-padded; zero-init,
// reset at kernel end -> graph-replay deterministic
__device__ unsigned g_flag[16][8 * 32];
__device__ unsigned g_fin[16 * 32];
// per-group r exchange buffer: [group][parity][batch][h]
__device__ float g_r[16 * 2 * 8 * HN];

typedef unsigned long long ull;

__device__ __forceinline__ ull ffma2(ull a, ull b, ull c) {
    ull d; asm("fma.rn.f32x2 %0,%1,%2,%3;" : "=l"(d) : "l"(a), "l"(b), "l"(c)); return d;
}
__device__ __forceinline__ ull pk2(float x, float y) {
    ull d; asm("mov.b64 %0,{%1,%2};" : "=l"(d) : "f"(x), "f"(y)); return d;
}
__device__ __forceinline__ void unpk2(ull a, float& lo, float& hi) {
    asm("mov.b64 {%0,%1},%2;" : "=f"(lo), "=f"(hi) : "l"(a));
}

// ---------------------------------------------------------------------------
// Single kernel: prologue computes this CTA's Wr slice (into SMEM) and fx
// slab (into g_fxp) with the bit-locked sequential chains; main loop is the
// scan with SMEM-resident Wr and L2 flag-sync across the 8-CTA group.
// ---------------------------------------------------------------------------
__global__ void __launch_bounds__(256, 1)
snn_kernel(const float* __restrict__ x,    const float* __restrict__ Win,
           const float* __restrict__ Wout, const float* __restrict__ pin,
           const float* __restrict__ pout, const float* __restrict__ l,
           float* __restrict__ out,
           float arg_ls, float arg_lm, float arg_ld,
           float rgain, float dtc, float tref)
{
    extern __shared__ __align__(16) unsigned char smraw[];
    ulonglong2* wr2_s = (ulonglong2*)smraw;                      // 8192 x 16B
    ull (*rdup)[8][HN] = (ull(*)[8][HN])(smraw + 131072);        // [2][8][512]
    float* wout_sh = (float*)(smraw + 196608);                   // 4096 floats
    float* part_y  = (float*)(smraw + 212992);                   // 64 floats
    // prologue scratch inside the rdup area (zeroed before main loop):
    float* ws  = (float*)(smraw + 131072);           // [64][33] Win slice
    float* lp  = (float*)(smraw + 131072 + 8448);    // [64][65] l*pin slice
    float* xst = (float*)(smraw + 131072 + 25088);   // [2][264] x stage

    const int tid = threadIdx.x;
    const unsigned u = blockIdx.x & 7;     // slice rank within group
    const int cl   = blockIdx.x >> 3;      // group id
    const int base = cl * 8;               // first batch of this group

    const float ls  = expf(arg_ls);
    const float lm  = expf(arg_lm);
    const float ldc = expf(arg_ld);
    const float olm = 1.0f - lm;

    // lane layout: warp w (0..7), lane ln. hp in 0..31, bb in 0..7.
    const int w  = tid >> 5, ln = tid & 31;
    const int hp = (w & 3) * 8 + (ln & 7);
    const int bb = (w >> 2) * 4 + (ln >> 3);

    float* fxslab = g_fxp + (size_t)blockIdx.x * (TS * 8 * 64);

    // ---- prologue A: stage Win slice + l*pin table ----
    for (int i = tid; i < 64 * IND; i += 256) {
        int hl = i >> 5, ii = i & 31;
        ws[hl * 33 + ii] = Win[((int)u * 64 + hl) * IND + ii];
    }
    for (int i = tid; i < 64 * PN; i += 256) {
        int hl = i >> 6, p = i & 63;
        lp[hl * 65 + p] = __fmul_rn(l[p], pin[((int)u * 64 + hl) * PN + p]);
    }
    for (int i = tid; i < HN * ON; i += 256)
        wout_sh[i] = Wout[(i & 7) * HN + (i >> 3)];
    __syncthreads();

    // ---- prologue B: Wr slice, 4 sequential-p chains per ulonglong2 ----
    // wr2_s[j2*32 + hpx] = (W[h0][j],W[h1][j] | W[h0][j+1],W[h1][j+1])
#pragma unroll 1
    for (int k = 0; k < 32; k++) {
        const int e   = tid + k * 256;
        const int j2  = e >> 5, hpx = e & 31;
        const int j   = 2 * j2;
        const float* l0 = lp + (2 * hpx) * 65;
        const float* l1 = l0 + 65;
        const float* p0 = pout + (size_t)j * PN;
        const float* p1 = p0 + PN;
        float w00 = 0.f, w10 = 0.f, w01 = 0.f, w11 = 0.f;
#pragma unroll
        for (int p = 0; p < PN; p++) {
            const float a0 = l0[p], a1 = l1[p];
            const float b0 = __ldg(p0 + p), b1 = __ldg(p1 + p);
            w00 = __fmaf_rn(a0, b0, w00);
            w10 = __fmaf_rn(a1, b0, w10);
            w01 = __fmaf_rn(a0, b1, w01);
            w11 = __fmaf_rn(a1, b1, w11);
        }
        wr2_s[e] = make_ulonglong2(pk2(w00, w10), pk2(w01, w11));
    }

    // ---- prologue C: fx slab, sequential-i chains, 2 t per stage ----
#pragma unroll 1
    for (int t0 = 0; t0 < TS; t0 += 2) {
        __syncthreads();
        {
            int i0 = tid;               // 512 floats, 2 per thread
            int tt = i0 >> 8, b = (i0 >> 5) & 7, ii = i0 & 31;
            xst[tt * 264 + b * 33 + ii] =
                x[((size_t)(t0 + tt) * BN + base + b) * IND + ii];
            i0 += 256;
            tt = i0 >> 8; b = (i0 >> 5) & 7; ii = i0 & 31;
            xst[tt * 264 + b * 33 + ii] =
                x[((size_t)(t0 + tt) * BN + base + b) * IND + ii];
        }
        __syncthreads();
        const float* w0 = ws + (2 * hp) * 33;
        const float* w1 = w0 + 33;
#pragma unroll
        for (int tt = 0; tt < 2; tt++) {
            const float* xv = xst + tt * 264 + bb * 33;
            float a0 = 0.f, a1 = 0.f;
#pragma unroll
            for (int i = 0; i < IND; i++) {
                const float xi = xv[i];
                a0 = __fmaf_rn(w0[i], xi, a0);
                a1 = __fmaf_rn(w1[i], xi, a1);
            }
            *(float2*)(fxslab + ((size_t)(t0 + tt) * 8 + bb) * 64 + 2 * hp) =
                make_float2(a0, a1);
        }
    }
    __syncthreads();

    // ---- zero parity-0 r buffers (also wipes prologue scratch region) ----
    for (int i = tid; i < 8 * HN; i += 256) ((ull*)rdup)[i] = 0ull;

    // neuron state for (h0,h1) x batch bb
    float I[2]   = {0.f, 0.f};
    float mem[2] = {0.f, 0.f};
    float s[2]   = {0.f, 0.f};
    float r[2]   = {0.f, 0.f};
    float tl[2]  = {-1.f, -1.f};

    const float2* fxp2 = (const float2*)fxslab;
    float2 fxc;

    float* gr_cl = g_r + (size_t)cl * 2 * 8 * HN;   // this group's buffer
    const int hg0 = (int)u * 64 + 2 * hp;           // global h of lane-low

    __syncthreads();
    fxc = fxp2[bb * 32 + hp];

#pragma unroll 1
    for (int t = 0; t < TS; t++) {
        const int par = t & 1, pn = par ^ 1;
        const int tn = (t < TS - 1) ? t + 1 : t;
        const float2 fxn = fxp2[(size_t)tn * 256 + bb * 32 + hp];  // prefetch

        // ONE FFMA2 chain, sequential in j (bit-exact vs scalar chain)
        const ulonglong2* d = (const ulonglong2*)&rdup[par][bb][0];
        ull acc = 0ull;
#pragma unroll 16
        for (int j2 = 0; j2 < 256; j2++) {
            const ulonglong2 q  = wr2_s[j2 * 32 + hp];
            const ulonglong2 rr = d[j2];
            acc = ffma2(q.x, rr.x, acc);
            acc = ffma2(q.y, rr.y, acc);
        }
        float rec[2], fxv[2];
        unpk2(acc, rec[0], rec[1]);
        fxv[0] = fxc.x; fxv[1] = fxc.y;

        const float ti = __fmul_rn(dtc, (float)t);
#pragma unroll
        for (int hh = 0; hh < 2; hh++) {
            I[hh] = __fadd_rn(__fadd_rn(__fmul_rn(ls, I[hh]), fxv[hh]), rec[hh]);
            const float notref = (ti > __fadd_rn(tl[hh], tref)) ? 1.0f : 0.0f;
            const float memn = __fmul_rn(__fmul_rn(notref,
                    __fadd_rn(__fmul_rn(lm, mem[hh]), __fmul_rn(olm, I[hh]))),
                    __fsub_rn(1.0f, s[hh]));
            r[hh] = __fadd_rn(__fmul_rn(ldc, r[hh]), __fmul_rn(rgain, s[hh]));
            const float snew = (__fsub_rn(memn, 1.0f) > 0.0f) ? 1.0f : 0.0f;
            tl[hh] = __fadd_rn(tl[hh], __fmul_rn(__fsub_rn(ti, tl[hh]), snew));
            mem[hh] = memn; s[hh] = snew;
        }
        fxc = fxn;

        // publish r(t): one coalesced STG.64 into this group's L2 buffer
        {
            float* dst = gr_cl + ((size_t)pn * 8 + bb) * HN + hg0;
            *(float2*)dst = make_float2(r[0], r[1]);
        }

        // ---- 8-flag group barrier through L2 (R10 variant) ----
        __syncthreads();          // order all threads' STGs before the release
        if (tid == 0) {
            unsigned* f = &g_flag[cl][u * 32];
            asm volatile("st.release.gpu.global.u32 [%0], %1;"
                         :: "l"(f), "r"((unsigned)(t + 1)) : "memory");
        }
        if (tid < 8) {
            const unsigned* f = &g_flag[cl][tid * 32];
            unsigned v;
            do {
                asm volatile("ld.acquire.gpu.global.u32 %0, [%1];"
                             : "=r"(v) : "l"(f) : "memory");
            } while (v < (unsigned)(t + 1));
        }
        __syncthreads();          // acquires visible to whole CTA

        // pull full r-set (16 KB) from L2, store duplicated pairs
        {
            const float4* src = (const float4*)(gr_cl + (size_t)pn * 8 * HN);
            float4 v[4];
#pragma unroll
            for (int i = 0; i < 4; i++) v[i] = __ldcg(src + tid + i * 256);
            ulonglong2* dst2 = (ulonglong2*)&rdup[pn][0][0];
#pragma unroll
            for (int i = 0; i < 4; i++) {
                const int idx = tid + i * 256;
                dst2[idx * 2 + 0] = make_ulonglong2(pk2(v[i].x, v[i].x),
                                                    pk2(v[i].y, v[i].y));
                dst2[idx * 2 + 1] = make_ulonglong2(pk2(v[i].z, v[i].z),
                                                    pk2(v[i].w, v[i].w));
            }
        }
        __syncthreads();   // rdup[pn] complete

        // y for batch (base+u) from full r(t) (same order as R6..R11)
        if (tid < 64) {
            const int o = tid & 7, seg = tid >> 3;
            const float* wq = wout_sh + (seg << 6) * 8 + o;
            const float* rr = (const float*)&rdup[pn][u][seg << 6];
            float e0 = 0.0f, e1 = 0.0f;
#pragma unroll
            for (int hh = 0; hh < 64; hh += 2) {
                e0 = __fmaf_rn(wq[hh << 3],       rr[hh * 2],       e0);
                e1 = __fmaf_rn(wq[(hh + 1) << 3], rr[(hh + 1) * 2], e1);
            }
            part_y[tid] = e0 + e1;
        }
        __syncthreads();
        if (tid < ON) {
            const float* q = part_y + tid;
            float v = ((q[0] + q[8]) + (q[16] + q[24])) +
                      ((q[32] + q[40]) + (q[48] + q[56]));
            out[((size_t)t * BN + base + u) * ON + tid] = v;
        }
    }

    // ---- reset barrier state for deterministic graph replay ----
    __syncthreads();
    if (tid == 0) {
        unsigned old = atomicAdd(&g_fin[cl * 32], 1u);
        if (old == 7u) {
#pragma unroll
            for (int k = 0; k < 8; k++) g_flag[cl][k * 32] = 0u;
            __threadfence();
            g_fin[cl * 32] = 0u;
        }
    }
}

extern "C" void kernel_launch(void* const* d_in, const int* in_sizes, int n_in,
                              void* d_out, int out_size) {
    const float* x    = (const float*)d_in[0];
    const float* Win  = (const float*)d_in[1];
    const float* Wout = (const float*)d_in[2];
    const float* pin  = (const float*)d_in[3];
    const float* pout = (const float*)d_in[4];
    const float* l    = (const float*)d_in[5];
    float* out = (float*)d_out;

    const float arg_ls = (float)(-0.002 / 0.01);
    const float arg_lm = (float)(-0.002 / 0.02);
    const float arg_ld = (float)(-0.002 / 0.03);
    const float rgain  = (float)(0.002 / 0.03);
    const float dtc    = (float)0.002;
    const float tref   = (float)(5.0 * 0.002);

    const int smem_bytes = 131072 + 65536 + 16384 + 256;   // 213248
    cudaFuncSetAttribute(snn_kernel, cudaFuncAttributeMaxDynamicSharedMemorySize,
                         smem_bytes);

    snn_kernel<<<BN, 256, smem_bytes>>>(x, Win, Wout, pin, pout, l, out,
                                        arg_ls, arg_lm, arg_ld, rgain, dtc, tref);
}